// round 7
// baseline (speedup 1.0000x reference)
#include <cuda_runtime.h>
#include <cstdint>

// Problem dims (fixed by the reference)
#define NB   4
#define NN   2048
#define FIN  128
#define NH   4
#define NC   32
#define HC   128            // NH*NC
#define ROWS (NB*NN)        // 8192 flattened (b,n)
#define MAXD 128            // neighbor-list capacity per row (avg degree ~21.5)
#define NEG  0.2f

// -------- device scratch (no allocations allowed) --------
__device__ float          g_feat [ROWS*HC];    // x@W, [row][h*32+c]  (4MB)
__device__ float          g_s    [ROWS*NH];    // a_src logits
__device__ float          g_d    [ROWS*NH];    // a_dst logits
__device__ float          g_denom[ROWS*NH];    // column softmax denominators
__device__ unsigned short g_nbr  [ROWS*MAXD];  // per-row neighbor indices
__device__ int            g_cnt  [ROWS];       // per-row neighbor counts

// -------- K1: feat = x @ W (+ logits + denom zeroing) --------
// 4 nodes/block, 128 threads, grid 2048 -> ~86% occupancy (grid was the limiter).
// Inner loop per k: 1 LDG(W, L1-resident) + 1 LDS.128 broadcast + 4 FFMA.
__global__ void __launch_bounds__(128) k_gemm(
        const float* __restrict__ x, const float* __restrict__ W,
        const float* __restrict__ asrc, const float* __restrict__ adst) {
    __shared__ float xs[FIN*4];        // [k][m], m=0..3
    const int t  = threadIdx.x;        // output column (h*32+c)
    const int n0 = blockIdx.x * 4;

    // fused: zero softmax denominators (first 256 blocks cover 32K floats)
    {
        int z = blockIdx.x * 128 + t;
        if (z < ROWS*NH) g_denom[z] = 0.0f;
    }

    // coalesced load: consecutive t -> consecutive k, same m
    for (int idx = t; idx < 4*FIN; idx += 128) {
        int m = idx >> 7, k = idx & 127;
        xs[k*4 + m] = x[(size_t)(n0 + m)*FIN + k];
    }
    __syncthreads();

    float4 acc = {0.f, 0.f, 0.f, 0.f};
    const float4* xv = (const float4*)xs;
#pragma unroll 8
    for (int k = 0; k < FIN; k++) {
        float wv = __ldg(&W[(size_t)k*HC + t]);
        float4 xm = xv[k];             // broadcast LDS.128
        acc.x = fmaf(xm.x, wv, acc.x);
        acc.y = fmaf(xm.y, wv, acc.y);
        acc.z = fmaf(xm.z, wv, acc.z);
        acc.w = fmaf(xm.w, wv, acc.w);
    }

    g_feat[(size_t)(n0+0)*HC + t] = acc.x;
    g_feat[(size_t)(n0+1)*HC + t] = acc.y;
    g_feat[(size_t)(n0+2)*HC + t] = acc.z;
    g_feat[(size_t)(n0+3)*HC + t] = acc.w;

    // fused attention logits: warp w == head h, lane == channel c
    const int h = t >> 5, lane = t & 31;
    const float as = asrc[h*NC + lane];
    const float ad = adst[h*NC + lane];
    float am[4] = {acc.x, acc.y, acc.z, acc.w};
#pragma unroll
    for (int m = 0; m < 4; m++) {
        float vs = am[m] * as;
        float vd = am[m] * ad;
#pragma unroll
        for (int o = 16; o; o >>= 1) {
            vs += __shfl_xor_sync(0xffffffffu, vs, o);
            vd += __shfl_xor_sync(0xffffffffu, vd, o);
        }
        if (lane == 0) {
            g_s[(n0 + m)*NH + h] = vs;
            g_d[(n0 + m)*NH + h] = vd;
        }
    }
}

// -------- K2a: scan adj row -> neighbor list (NO dependence on gemm) --------
__global__ void __launch_bounds__(512) k_scan(const float4* __restrict__ adj4) {
    __shared__ int cnt_s;
    __shared__ unsigned short list_s[MAXD];
    const int row = blockIdx.x;           // flattened (b,i)
    const int i   = row & (NN - 1);
    const int t   = threadIdx.x;

    if (t == 0) cnt_s = 0;

    // unconditional batched LDG.128 (full row covered by the block)
    float4 v = adj4[(size_t)row * (NN/4) + t];
    __syncthreads();

    const int j0 = t * 4;
    float vals[4] = {v.x, v.y, v.z, v.w};
#pragma unroll
    for (int c = 0; c < 4; c++) {
        int j = j0 + c;
        if (vals[c] != 0.0f || j == i) {   // self-loop always present
            int p = atomicAdd(&cnt_s, 1);
            if (p < MAXD) list_s[p] = (unsigned short)j;
        }
    }
    __syncthreads();

    const int cnt = min(cnt_s, MAXD);
    if (t == 0) g_cnt[row] = cnt;
    if (t < cnt) g_nbr[(size_t)row*MAXD + t] = list_s[t];
}

// -------- K2b: column softmax denominators (needs gemm + scan) --------
// warp-per-row: denom[b,j,h] += exp(lrelu(s[b,i,h] + d[b,j,h]))
__global__ void __launch_bounds__(256) k_denom() {
    const int warp = threadIdx.x >> 5, lane = threadIdx.x & 31;
    const int row  = blockIdx.x * 8 + warp;
    const int b    = row >> 11;
    const int cnt  = g_cnt[row];

    float s[NH];
#pragma unroll
    for (int h = 0; h < NH; h++) s[h] = g_s[row*NH + h];

    for (int q = lane; q < cnt*NH; q += 32) {
        int k = q >> 2, h = q & 3;
        int jr = (b << 11) | g_nbr[(size_t)row*MAXD + k];
        float a = s[h] + g_d[jr*NH + h];
        float e = __expf(a > 0.0f ? a : NEG * a);
        atomicAdd(&g_denom[jr*NH + h], e);
    }
}

// -------- K3: warp-per-row float4 gather --------
#define OW 8   // rows (warps) per block
__global__ void __launch_bounds__(32*OW) k_out(float4* __restrict__ out,
                                               const float* __restrict__ bias) {
    __shared__ unsigned short list_s[OW][MAXD];
    __shared__ float w_s[OW][MAXD*NH];     // [k*4+h]
    const int warp = threadIdx.x >> 5, lane = threadIdx.x & 31;
    const int row  = blockIdx.x * OW + warp;
    const int b    = row >> 11;
    const int cnt  = g_cnt[row];           // broadcast load

    unsigned short* list = list_s[warp];
    float*          w    = w_s[warp];

    for (int k = lane; k < cnt; k += 32) list[k] = g_nbr[(size_t)row*MAXD + k];
    __syncwarp();

    for (int q = lane; q < cnt*NH; q += 32) {
        int k = q >> 2, h = q & 3;
        int jr = (b << 11) | list[k];
        float a = g_s[row*NH + h] + g_d[jr*NH + h];
        float e = __expf(a > 0.0f ? a : NEG * a);
        w[q] = __fdividef(e, g_denom[jr*NH + h]);
    }
    __syncwarp();

    const int h4 = (lane >> 3) & 3;        // head for this lane's channel group
    const float4* feat4 = (const float4*)g_feat;
    const size_t bbase = (size_t)(b << 11) * 32;   // float4 units per row

    float4 a0 = {0,0,0,0}, a1 = {0,0,0,0}, a2 = {0,0,0,0}, a3 = {0,0,0,0};
    int k = 0;
    for (; k + 4 <= cnt; k += 4) {
        int j0 = list[k+0], j1 = list[k+1], j2 = list[k+2], j3 = list[k+3];
        float4 f0 = feat4[bbase + (size_t)j0*32 + lane];
        float4 f1 = feat4[bbase + (size_t)j1*32 + lane];
        float4 f2 = feat4[bbase + (size_t)j2*32 + lane];
        float4 f3 = feat4[bbase + (size_t)j3*32 + lane];
        float w0 = w[(k+0)*NH + h4], w1 = w[(k+1)*NH + h4];
        float w2 = w[(k+2)*NH + h4], w3 = w[(k+3)*NH + h4];
        a0.x = fmaf(w0, f0.x, a0.x); a0.y = fmaf(w0, f0.y, a0.y);
        a0.z = fmaf(w0, f0.z, a0.z); a0.w = fmaf(w0, f0.w, a0.w);
        a1.x = fmaf(w1, f1.x, a1.x); a1.y = fmaf(w1, f1.y, a1.y);
        a1.z = fmaf(w1, f1.z, a1.z); a1.w = fmaf(w1, f1.w, a1.w);
        a2.x = fmaf(w2, f2.x, a2.x); a2.y = fmaf(w2, f2.y, a2.y);
        a2.z = fmaf(w2, f2.z, a2.z); a2.w = fmaf(w2, f2.w, a2.w);
        a3.x = fmaf(w3, f3.x, a3.x); a3.y = fmaf(w3, f3.y, a3.y);
        a3.z = fmaf(w3, f3.z, a3.z); a3.w = fmaf(w3, f3.w, a3.w);
    }
    for (; k < cnt; k++) {
        int j = list[k];
        float4 f = feat4[bbase + (size_t)j*32 + lane];
        float wv = w[k*NH + h4];
        a0.x = fmaf(wv, f.x, a0.x); a0.y = fmaf(wv, f.y, a0.y);
        a0.z = fmaf(wv, f.z, a0.z); a0.w = fmaf(wv, f.w, a0.w);
    }

    const float4 bv = ((const float4*)bias)[lane];
    float4 r;
    r.x = (a0.x + a1.x) + (a2.x + a3.x) + bv.x;
    r.y = (a0.y + a1.y) + (a2.y + a3.y) + bv.y;
    r.z = (a0.z + a1.z) + (a2.z + a3.z) + bv.z;
    r.w = (a0.w + a1.w) + (a2.w + a3.w) + bv.w;
    out[(size_t)row*32 + lane] = r;
}

// -------- launch: fork adj scan onto a side stream, overlap with GEMM --------
extern "C" void kernel_launch(void* const* d_in, const int* in_sizes, int n_in,
                              void* d_out, int out_size) {
    const float* x    = (const float*)d_in[0];   // [B,N,FIN]
    const float* adj  = (const float*)d_in[1];   // [B,N,N]
    const float* W    = (const float*)d_in[2];   // [FIN,HC]
    const float* asrc = (const float*)d_in[3];   // [H,C]
    const float* adst = (const float*)d_in[4];   // [H,C]
    const float* bias = (const float*)d_in[5];   // [HC]
    float4* out = (float4*)d_out;                // [B,N,HC]

    // Host-side objects only (no device memory). kernel_launch is invoked just
    // for correctness + capture, so per-call creation is cheap and stateless.
    cudaStream_t s2;
    cudaEvent_t ev_fork, ev_join;
    cudaStreamCreateWithFlags(&s2, cudaStreamNonBlocking);
    cudaEventCreateWithFlags(&ev_fork, cudaEventDisableTiming);
    cudaEventCreateWithFlags(&ev_join, cudaEventDisableTiming);

    // fork: adj scan is independent of the GEMM
    cudaEventRecord(ev_fork, 0);
    cudaStreamWaitEvent(s2, ev_fork, 0);
    k_scan<<<ROWS, 512, 0, s2>>>((const float4*)adj);
    cudaEventRecord(ev_join, s2);

    k_gemm<<<ROWS/4, 128>>>(x, W, asrc, adst);   // also zeros g_denom

    // join: denom needs gemm (stream order) + scan (event)
    cudaStreamWaitEvent(0, ev_join, 0);
    k_denom<<<ROWS/8, 256>>>();
    k_out  <<<ROWS/OW, 32*OW>>>(out, bias);
}

// round 8
// speedup vs baseline: 1.2360x; 1.2360x over previous
#include <cuda_runtime.h>
#include <cstdint>

// Problem dims (fixed by the reference)
#define NB   4
#define NN   2048
#define FIN  128
#define NH   4
#define NC   32
#define HC   128            // NH*NC
#define ROWS (NB*NN)        // 8192 flattened (b,n)
#define MAXD 128            // neighbor-list capacity per row (avg degree ~21.5)
#define NEG  0.2f
#define GEMMB (ROWS/8)      // 1024 gemm blocks (8 nodes each)

// -------- device scratch (no allocations allowed) --------
__device__ float          g_feat [ROWS*HC];       // x@W (4MB)
__device__ float          g_s    [ROWS*NH];       // a_src logits
__device__ float          g_d    [ROWS*NH];       // a_dst logits
__device__ float          g_denom[ROWS*NH];       // column softmax denominators
__device__ float          g_w    [ROWS*MAXD*NH];  // per-edge exp numerators (16MB)
__device__ unsigned short g_nbr  [ROWS*MAXD];     // per-row neighbor indices
__device__ int            g_cnt  [ROWS];          // per-row neighbor counts

// -------- K1: FUSED  [blocks 0..GEMMB): gemm+logits+zero] [blocks GEMMB..): adj scan] --------
// Block specialization gives hardware-guaranteed overlap of the FFMA-bound GEMM
// with the DRAM-bound adjacency scan (stream fork/join replayed serially).
__global__ void __launch_bounds__(128) k_front(
        const float*  __restrict__ x,    const float* __restrict__ W,
        const float*  __restrict__ asrc, const float* __restrict__ adst,
        const float4* __restrict__ adj4) {
    const int t = threadIdx.x;

    if (blockIdx.x < GEMMB) {
        // ---------------- GEMM: 8 nodes/block, thread t = output column ----------------
        __shared__ float xs[FIN*8];            // [k][m], 4KB
        const int n0 = blockIdx.x * 8;

        // fused: zero softmax denominators (first 256 gemm blocks cover 32K floats)
        {
            int z = blockIdx.x * 128 + t;
            if (z < ROWS*NH) g_denom[z] = 0.0f;
        }

        for (int idx = t; idx < 8*FIN; idx += 128) {
            int m = idx >> 7, k = idx & 127;
            xs[k*8 + m] = x[(size_t)(n0 + m)*FIN + k];
        }
        __syncthreads();

        float4 a0 = {0,0,0,0}, a1 = {0,0,0,0};
        const float4* xv = (const float4*)xs;
#pragma unroll 8
        for (int k = 0; k < FIN; k++) {
            float wv = __ldg(&W[(size_t)k*HC + t]);
            float4 x0 = xv[k*2+0];             // broadcast LDS.128
            float4 x1 = xv[k*2+1];
            a0.x = fmaf(x0.x, wv, a0.x); a0.y = fmaf(x0.y, wv, a0.y);
            a0.z = fmaf(x0.z, wv, a0.z); a0.w = fmaf(x0.w, wv, a0.w);
            a1.x = fmaf(x1.x, wv, a1.x); a1.y = fmaf(x1.y, wv, a1.y);
            a1.z = fmaf(x1.z, wv, a1.z); a1.w = fmaf(x1.w, wv, a1.w);
        }

        float am[8] = {a0.x,a0.y,a0.z,a0.w,a1.x,a1.y,a1.z,a1.w};
#pragma unroll
        for (int m = 0; m < 8; m++)
            g_feat[(size_t)(n0+m)*HC + t] = am[m];

        // fused attention logits: warp == head h, lane == channel c
        const int h = t >> 5, lane = t & 31;
        const float as = asrc[h*NC + lane];
        const float ad = adst[h*NC + lane];
#pragma unroll
        for (int m = 0; m < 8; m++) {
            float vs = am[m] * as;
            float vd = am[m] * ad;
#pragma unroll
            for (int o = 16; o; o >>= 1) {
                vs += __shfl_xor_sync(0xffffffffu, vs, o);
                vd += __shfl_xor_sync(0xffffffffu, vd, o);
            }
            if (lane == 0) {
                g_s[(n0 + m)*NH + h] = vs;
                g_d[(n0 + m)*NH + h] = vd;
            }
        }
    } else {
        // ---------------- SCAN: one adj row/block, 4 batched LDG.128 per thread ----------------
        __shared__ int cnt_s;
        __shared__ unsigned short list_s[MAXD];
        const int row = blockIdx.x - GEMMB;    // flattened (b,i)
        const int i   = row & (NN - 1);

        if (t == 0) cnt_s = 0;

        const float4* base = adj4 + (size_t)row * (NN/4);
        float4 v0 = base[t      ];
        float4 v1 = base[t + 128];
        float4 v2 = base[t + 256];
        float4 v3 = base[t + 384];
        __syncthreads();

        float vals[16] = {v0.x,v0.y,v0.z,v0.w, v1.x,v1.y,v1.z,v1.w,
                          v2.x,v2.y,v2.z,v2.w, v3.x,v3.y,v3.z,v3.w};
#pragma unroll
        for (int u = 0; u < 4; u++) {
#pragma unroll
            for (int c = 0; c < 4; c++) {
                int j = (t + u*128)*4 + c;
                if (vals[u*4+c] != 0.0f || j == i) {   // self-loop always present
                    int p = atomicAdd(&cnt_s, 1);
                    if (p < MAXD) list_s[p] = (unsigned short)j;
                }
            }
        }
        __syncthreads();

        const int cnt = min(cnt_s, MAXD);
        if (t == 0) g_cnt[row] = cnt;
        if (t < cnt) g_nbr[(size_t)row*MAXD + t] = list_s[t];
    }
}

// -------- K2: column softmax denominators + stash per-edge exp numerators --------
__global__ void __launch_bounds__(256) k_denom() {
    const int warp = threadIdx.x >> 5, lane = threadIdx.x & 31;
    const int row  = blockIdx.x * 8 + warp;
    const int b    = row >> 11;
    const int cnt  = g_cnt[row];

    float s[NH];
#pragma unroll
    for (int h = 0; h < NH; h++) s[h] = g_s[row*NH + h];

    for (int q = lane; q < cnt*NH; q += 32) {
        int k = q >> 2, h = q & 3;
        int jr = (b << 11) | g_nbr[(size_t)row*MAXD + k];
        float a = s[h] + g_d[jr*NH + h];
        float e = __expf(a > 0.0f ? a : NEG * a);
        g_w[(size_t)row*MAXD*NH + q] = e;            // coalesced stash
        atomicAdd(&g_denom[jr*NH + h], e);
    }
}

// -------- K3: warp-per-row float4 gather --------
#define OW 8   // rows (warps) per block
__global__ void __launch_bounds__(32*OW, 6) k_out(float4* __restrict__ out,
                                                  const float* __restrict__ bias) {
    __shared__ unsigned short list_s[OW][MAXD];
    __shared__ float w_s[OW][MAXD*NH];     // [k*4+h]
    const int warp = threadIdx.x >> 5, lane = threadIdx.x & 31;
    const int row  = blockIdx.x * OW + warp;
    const int b    = row >> 11;
    const int cnt  = g_cnt[row];           // broadcast load

    unsigned short* list = list_s[warp];
    float*          w    = w_s[warp];

    for (int k = lane; k < cnt; k += 32) list[k] = g_nbr[(size_t)row*MAXD + k];
    __syncwarp();

    // weights: coalesced numerator load + scattered denom divide (exp precomputed)
    for (int q = lane; q < cnt*NH; q += 32) {
        int k = q >> 2, h = q & 3;
        int jr = (b << 11) | list[k];
        w[q] = __fdividef(g_w[(size_t)row*MAXD*NH + q], g_denom[jr*NH + h]);
    }
    __syncwarp();

    const int h4 = (lane >> 3) & 3;        // head for this lane's channel group
    const float4* feat4 = (const float4*)g_feat;
    const size_t bbase = (size_t)(b << 11) * 32;   // float4 units per row

    float4 a0 = {0,0,0,0}, a1 = {0,0,0,0}, a2 = {0,0,0,0}, a3 = {0,0,0,0};
    int k = 0;
    for (; k + 4 <= cnt; k += 4) {
        int j0 = list[k+0], j1 = list[k+1], j2 = list[k+2], j3 = list[k+3];
        float4 f0 = feat4[bbase + (size_t)j0*32 + lane];
        float4 f1 = feat4[bbase + (size_t)j1*32 + lane];
        float4 f2 = feat4[bbase + (size_t)j2*32 + lane];
        float4 f3 = feat4[bbase + (size_t)j3*32 + lane];
        float w0 = w[(k+0)*NH + h4], w1 = w[(k+1)*NH + h4];
        float w2 = w[(k+2)*NH + h4], w3 = w[(k+3)*NH + h4];
        a0.x = fmaf(w0, f0.x, a0.x); a0.y = fmaf(w0, f0.y, a0.y);
        a0.z = fmaf(w0, f0.z, a0.z); a0.w = fmaf(w0, f0.w, a0.w);
        a1.x = fmaf(w1, f1.x, a1.x); a1.y = fmaf(w1, f1.y, a1.y);
        a1.z = fmaf(w1, f1.z, a1.z); a1.w = fmaf(w1, f1.w, a1.w);
        a2.x = fmaf(w2, f2.x, a2.x); a2.y = fmaf(w2, f2.y, a2.y);
        a2.z = fmaf(w2, f2.z, a2.z); a2.w = fmaf(w2, f2.w, a2.w);
        a3.x = fmaf(w3, f3.x, a3.x); a3.y = fmaf(w3, f3.y, a3.y);
        a3.z = fmaf(w3, f3.z, a3.z); a3.w = fmaf(w3, f3.w, a3.w);
    }
    for (; k < cnt; k++) {
        int j = list[k];
        float4 f = feat4[bbase + (size_t)j*32 + lane];
        float wv = w[k*NH + h4];
        a0.x = fmaf(wv, f.x, a0.x); a0.y = fmaf(wv, f.y, a0.y);
        a0.z = fmaf(wv, f.z, a0.z); a0.w = fmaf(wv, f.w, a0.w);
    }

    const float4 bv = ((const float4*)bias)[lane];
    float4 r;
    r.x = (a0.x + a1.x) + (a2.x + a3.x) + bv.x;
    r.y = (a0.y + a1.y) + (a2.y + a3.y) + bv.y;
    r.z = (a0.z + a1.z) + (a2.z + a3.z) + bv.z;
    r.w = (a0.w + a1.w) + (a2.w + a3.w) + bv.w;
    out[(size_t)row*32 + lane] = r;
}

// -------- launch --------
extern "C" void kernel_launch(void* const* d_in, const int* in_sizes, int n_in,
                              void* d_out, int out_size) {
    const float* x    = (const float*)d_in[0];   // [B,N,FIN]
    const float* adj  = (const float*)d_in[1];   // [B,N,N]
    const float* W    = (const float*)d_in[2];   // [FIN,HC]
    const float* asrc = (const float*)d_in[3];   // [H,C]
    const float* adst = (const float*)d_in[4];   // [H,C]
    const float* bias = (const float*)d_in[5];   // [HC]
    float4* out = (float4*)d_out;                // [B,N,HC]

    k_front<<<GEMMB + ROWS, 128>>>(x, W, asrc, adst, (const float4*)adj);
    k_denom<<<ROWS/8, 256>>>();
    k_out  <<<ROWS/OW, 32*OW>>>(out, bias);
}